// round 3
// baseline (speedup 1.0000x reference)
#include <cuda_runtime.h>
#include <stdint.h>

// ============================================================================
// Fused colorization L2Loss: LUT build + grid barrier + weighted loss, 1 kernel.
//   loss = mean_b sum_{c,h,w} (in-tgt)^2 * prior[argmin_q d2(tgt_px, gamut[q])]
//
// Phase 1 (build): 8 warps/block x 512 blocks = 4096 warps, one per 64x64 cell
//   over [-1,1]^2. Candidates = bins with d(center,bin) <= dmin(center)+diag
//   (provably contains the true NN of every point in the cell). Up to 4 packed
//   into one uint64 (dup-padded; slot3=0xFFFF => overflow list fallback).
// Barrier: atomic arrive + spin (all 512 blocks co-resident: 48 regs, 8.6KB smem
//   -> 4 blocks/SM fits; 512 <= 148*4).
// Phase 2 (loss): 2 px/thread, float2 loads, exact strict-< argmin over the
//   packed candidates, hierarchical reduce + atomicAdd.
// ============================================================================

#define LGRID 64
#define NCELL (LGRID * LGRID)
#define CAP   32
#define MAXQ  512
#define NBLK  512
#define NTHR  256

__device__ unsigned long long g_pack[NCELL];
__device__ unsigned short     g_cand[NCELL * CAP];
__device__ unsigned int       g_cnt[NCELL];
__device__ unsigned int       g_arrive;   // zero-init; reset at kernel end
__device__ unsigned int       g_done;

__global__ void __launch_bounds__(NTHR) fused_loss_kernel(
    const float*  __restrict__ input,
    const float*  __restrict__ target,
    const float2* __restrict__ gamut,
    const float*  __restrict__ prior,
    float*        __restrict__ out,
    int Q)
{
    __shared__ float4 sf[MAXQ];                 // (-2gx, -2gy, |g|^2+16, prior)
    __shared__ unsigned short scand[8][CAP];
    __shared__ float ws[8];

    for (int i = threadIdx.x; i < Q; i += NTHR) {
        const float2 g = gamut[i];
        sf[i] = make_float4(-2.0f * g.x, -2.0f * g.y,
                            fmaf(g.x, g.x, fmaf(g.y, g.y, 16.0f)),
                            prior[i]);
    }
    __syncthreads();

    // ---------------- Phase 1: build LUT (one warp per cell) ----------------
    const int warp = threadIdx.x >> 5;
    const int lane = threadIdx.x & 31;
    const int cell = blockIdx.x * 8 + warp;     // 512*8 = 4096 exactly

    {
        const int ix = cell & (LGRID - 1);
        const int iy = cell >> 6;
        const float cellw = 2.0f / (float)LGRID;
        const float cx = -1.0f + ((float)ix + 0.5f) * cellw;
        const float cy = -1.0f + ((float)iy + 0.5f) * cellw;
        const float c2 = fmaf(cx, cx, cy * cy);
        const float diag = 0.04450f;            // cell diagonal 0.044194 + pad

        // score = d2 + 16 - c2  (same fma form used in the loss phase)
        float scv[(MAXQ + 31) / 32];
        float smin = 1e30f;
        const int nIter = (Q + 31) >> 5;
        #pragma unroll
        for (int j = 0; j < (MAXQ + 31) / 32; j++) {
            if (j >= nIter) break;
            const int b = (j << 5) + lane;
            float sc = 1e30f;
            if (b < Q) {
                const float4 g = sf[b];
                sc = fmaf(g.x, cx, fmaf(g.y, cy, g.z));
            }
            scv[j] = sc;
            smin = fminf(smin, sc);
        }
        #pragma unroll
        for (int off = 16; off; off >>= 1)
            smin = fminf(smin, __shfl_xor_sync(0xFFFFFFFFu, smin, off));

        const float d2min = fmaxf(smin - 16.0f + c2, 0.0f);
        const float s     = sqrtf(d2min) + diag;
        const float thr   = fmaf(s, s, 16.0f - c2) + 2e-5f;  // score threshold

        int base = 0;
        for (int j = 0; j < nIter; j++) {
            const bool take = (scv[j] <= thr);
            const unsigned m = __ballot_sync(0xFFFFFFFFu, take);
            if (take) {
                const int pos = base + __popc(m & ((1u << lane) - 1u));
                if (pos < CAP)
                    scand[warp][pos] = (unsigned short)((j << 5) + lane);
            }
            base += __popc(m);
        }
        __syncwarp();

        if (base > 4) {                          // rare: write overflow list
            const int nw = min(base, CAP);
            for (int j = lane; j < nw; j += 32)
                g_cand[cell * CAP + j] = scand[warp][j];
            if (lane == 0) g_cnt[cell] = (unsigned)base;
        }
        if (lane == 0) {
            const unsigned long long i0 = scand[warp][0];   // base >= 1 always
            const unsigned long long i1 = (base > 1) ? scand[warp][1] : i0;
            const unsigned long long i2 = (base > 2) ? scand[warp][2] : i0;
            unsigned long long i3       = (base > 3) ? scand[warp][3] : i0;
            if (base > 4) i3 = 0xFFFFull;
            g_pack[cell] = i0 | (i1 << 16) | (i2 << 32) | (i3 << 48);
        }
    }

    if (blockIdx.x == 0 && threadIdx.x == 0) out[0] = 0.0f;

    // ---------------- Grid barrier (all blocks co-resident) ----------------
    __syncthreads();
    if (threadIdx.x == 0) {
        __threadfence();                         // release block's g_pack/out writes
        atomicAdd(&g_arrive, 1u);
        unsigned v;
        do {
            v = atomicAdd(&g_arrive, 0u);
            if (v < NBLK) __nanosleep(32);
        } while (v < NBLK);
        __threadfence();                         // acquire
    }
    __syncthreads();

    // ---------------- Phase 2: loss, 2 consecutive pixels per thread --------
    const int tid   = blockIdx.x * NTHR + threadIdx.x;  // 0..131071
    const int q     = tid << 1;
    const int bb    = q >> 16;
    const int n     = q & 65535;
    const int base0 = bb * 131072 + n;

    const float2 tv0 = *(const float2*)(target + base0);
    const float2 tv1 = *(const float2*)(target + base0 + 65536);
    const float2 iv0 = *(const float2*)(input  + base0);
    const float2 iv1 = *(const float2*)(input  + base0 + 65536);

    const float ta[2] = {tv0.x, tv0.y};
    const float tb[2] = {tv1.x, tv1.y};
    const float ia[2] = {iv0.x, iv0.y};
    const float ib[2] = {iv1.x, iv1.y};

    float acc = 0.0f;

    #pragma unroll
    for (int k = 0; k < 2; k++) {
        int ix = (int)((ta[k] + 1.0f) * ((float)LGRID * 0.5f));
        int iy = (int)((tb[k] + 1.0f) * ((float)LGRID * 0.5f));
        ix = min(max(ix, 0), LGRID - 1);
        iy = min(max(iy, 0), LGRID - 1);
        const int cc = (iy << 6) | ix;

        const unsigned long long p = g_pack[cc];
        const unsigned a0 = (unsigned)(p & 0xFFFFull);
        const unsigned a1 = (unsigned)((p >> 16) & 0xFFFFull);
        const unsigned a2 = (unsigned)((p >> 32) & 0xFFFFull);
        const unsigned a3 = (unsigned)(p >> 48);

        float    bestSc;
        unsigned bestIdx;

        if (a3 != 0xFFFFu) {
            float4 g = sf[a0];
            bestSc  = fmaf(g.x, ta[k], fmaf(g.y, tb[k], g.z));
            bestIdx = a0;
            g = sf[a1];
            float s1 = fmaf(g.x, ta[k], fmaf(g.y, tb[k], g.z));
            if (s1 < bestSc) { bestSc = s1; bestIdx = a1; }
            g = sf[a2];
            float s2 = fmaf(g.x, ta[k], fmaf(g.y, tb[k], g.z));
            if (s2 < bestSc) { bestSc = s2; bestIdx = a2; }
            g = sf[a3];
            float s3 = fmaf(g.x, ta[k], fmaf(g.y, tb[k], g.z));
            if (s3 < bestSc) { bestSc = s3; bestIdx = a3; }
        } else {
            bestSc = 1e30f; bestIdx = 0;
            const unsigned cnt = g_cnt[cc];
            if (cnt <= CAP) {
                const unsigned short* cl = &g_cand[cc * CAP];
                for (unsigned j = 0; j < cnt; j++) {
                    const unsigned bi = (unsigned)cl[j];
                    const float4 g = sf[bi];
                    const float sc = fmaf(g.x, ta[k], fmaf(g.y, tb[k], g.z));
                    if (sc < bestSc) { bestSc = sc; bestIdx = bi; }
                }
            } else {
                for (int bi = 0; bi < Q; bi++) {
                    const float4 g = sf[bi];
                    const float sc = fmaf(g.x, ta[k], fmaf(g.y, tb[k], g.z));
                    if (sc < bestSc) { bestSc = sc; bestIdx = (unsigned)bi; }
                }
            }
        }

        const float w  = sf[bestIdx].w;
        const float d0 = ia[k] - ta[k];
        const float d1 = ib[k] - tb[k];
        acc += w * fmaf(d0, d0, d1 * d1);
    }

    acc *= 0.25f;   // mean over batch b = 4

    #pragma unroll
    for (int off = 16; off; off >>= 1)
        acc += __shfl_xor_sync(0xFFFFFFFFu, acc, off);

    if (lane == 0) ws[warp] = acc;
    __syncthreads();
    if (threadIdx.x < 8) {
        float v = ws[threadIdx.x];
        #pragma unroll
        for (int off = 4; off; off >>= 1)
            v += __shfl_xor_sync(0xFFu, v, off);
        if (threadIdx.x == 0) atomicAdd(out, v);
    }

    // ---------------- reset barrier state for next graph replay -------------
    if (threadIdx.x == 0) {
        __threadfence();
        if (atomicAdd(&g_done, 1u) == NBLK - 1) {   // last block out
            g_arrive = 0;
            g_done   = 0;
            __threadfence();
        }
    }
}

// ---------------------------------------------------------------------------
extern "C" void kernel_launch(void* const* d_in, const int* in_sizes, int n_in,
                              void* d_out, int out_size)
{
    const float*  input  = (const float*)d_in[0];
    const float*  target = (const float*)d_in[1];
    const float2* gamut  = (const float2*)d_in[2];   // [Q,2]
    const float*  prior  = (const float*)d_in[3];    // [Q]
    float* out = (float*)d_out;
    const int Q = in_sizes[3];                        // 313

    fused_loss_kernel<<<NBLK, NTHR>>>(input, target, gamut, prior, out, Q);
}